// round 5
// baseline (speedup 1.0000x reference)
#include <cuda_runtime.h>
#include <cstddef>

#define TT   512
#define NB   4096
#define BC   32          // batch elements per CTA
#define NTH  256
#define HS2  68          // padded dup-row stride (floats): 16B-aligned, rotates banks for STS

typedef unsigned long long u64;

struct SmemT {
    float4 whh0[64 * 64];   // [k][u] -> gates (i,f,g,o) of unit u
    float4 wih1[64 * 64];
    float4 whh1[64 * 64];
    float  h0[64 * HS2];    // [k][2*b..2*b+1] duplicated (h,h)
    float  h1[64 * HS2];
    float  xs[6 * 32];      // x_t staging, non-duplicated [j][b]
};

// ---- f32x2 packed math (Blackwell FFMA2: 2 fp32 FMAs / instr) ----
__device__ __forceinline__ void fma2(u64& d, u64 a, u64 b) {
    asm("fma.rn.f32x2 %0, %1, %2, %0;" : "+l"(d) : "l"(a), "l"(b));
}
__device__ __forceinline__ u64 pack2(float a, float b) {
    u64 v; asm("mov.b64 %0, {%1, %2};" : "=l"(v) : "f"(a), "f"(b)); return v;
}
__device__ __forceinline__ float2 unpack2(u64 v) {
    float2 r; asm("mov.b64 {%0, %1}, %2;" : "=f"(r.x), "=f"(r.y) : "l"(v)); return r;
}

__device__ __forceinline__ float sigm(float x) {
    float e = __expf(-x);
    return __fdividef(1.0f, 1.0f + e);
}
__device__ __forceinline__ float tanh_f(float x) {
    return fmaf(2.0f, sigm(2.0f * x), -1.0f);
}

// one k-iter: 1 weight LDS.128 (-> 2 f32x2), 4 broadcast LDS.128 (8 dup'd h), 16 FFMA2
__device__ __forceinline__ void macK(u64* aif, u64* ago,
                                     const float* __restrict__ hrow,
                                     const float4* __restrict__ wp) {
    ulonglong2 w = *(const ulonglong2*)wp;             // w.x=(wi,wf), w.y=(wg,wo)
    const ulonglong2* hp = (const ulonglong2*)hrow;    // (h,h) pairs
    ulonglong2 p0 = hp[0], p1 = hp[1], p2 = hp[2], p3 = hp[3];
    fma2(aif[0], p0.x, w.x); fma2(ago[0], p0.x, w.y);
    fma2(aif[1], p0.y, w.x); fma2(ago[1], p0.y, w.y);
    fma2(aif[2], p1.x, w.x); fma2(ago[2], p1.x, w.y);
    fma2(aif[3], p1.y, w.x); fma2(ago[3], p1.y, w.y);
    fma2(aif[4], p2.x, w.x); fma2(ago[4], p2.x, w.y);
    fma2(aif[5], p2.y, w.x); fma2(ago[5], p2.y, w.y);
    fma2(aif[6], p3.x, w.x); fma2(ago[6], p3.x, w.y);
    fma2(aif[7], p3.y, w.x); fma2(ago[7], p3.y, w.y);
}

__device__ __forceinline__ void epilogue(u64* aif, u64* ago, float* c,
                                         float* __restrict__ hdst) {
#pragma unroll
    for (int b = 0; b < 8; b++) {
        float2 gif = unpack2(aif[b]);     // (i, f) pre-activations
        float2 ggo = unpack2(ago[b]);     // (g, o)
        float i_ = sigm(gif.x);
        float f_ = sigm(gif.y);
        float g_ = tanh_f(ggo.x);
        float o_ = sigm(ggo.y);
        float cc = fmaf(f_, c[b], i_ * g_);
        c[b] = cc;
        float h = o_ * tanh_f(cc);
        *(float2*)&hdst[2 * b] = make_float2(h, h);   // duplicated store
    }
}

__global__ void __launch_bounds__(NTH, 1) lstm2_kernel(
    const float* __restrict__ x,
    const float* __restrict__ Wih0, const float* __restrict__ Whh0,
    const float* __restrict__ bih0, const float* __restrict__ bhh0,
    const float* __restrict__ Wih1, const float* __restrict__ Whh1,
    const float* __restrict__ bih1, const float* __restrict__ bhh1,
    const float* __restrict__ Wfc,  const float* __restrict__ bfc,
    float* __restrict__ out)
{
    extern __shared__ char smraw[];
    SmemT* s = reinterpret_cast<SmemT*>(smraw);
    const int tid    = threadIdx.x;
    const int batch0 = blockIdx.x * BC;

    // ---- one-time weight staging: gate-interleave so each unit's (i,f,g,o) is a float4 ----
    for (int idx = tid; idx < 64 * 64; idx += NTH) {
        int k = idx >> 6, u = idx & 63;
        s->whh0[idx] = make_float4(Whh0[u * 64 + k], Whh0[(64 + u) * 64 + k],
                                   Whh0[(128 + u) * 64 + k], Whh0[(192 + u) * 64 + k]);
        s->wih1[idx] = make_float4(Wih1[u * 64 + k], Wih1[(64 + u) * 64 + k],
                                   Wih1[(128 + u) * 64 + k], Wih1[(192 + u) * 64 + k]);
        s->whh1[idx] = make_float4(Whh1[u * 64 + k], Whh1[(64 + u) * 64 + k],
                                   Whh1[(128 + u) * 64 + k], Whh1[(192 + u) * 64 + k]);
    }
    for (int idx = tid; idx < 64 * HS2; idx += NTH) { s->h0[idx] = 0.f; s->h1[idx] = 0.f; }

    // thread mapping: 1 unit x 8 batches
    const int lane = tid & 31;
    const int warp = tid >> 5;
    const int u    = (warp & 1) * 32 + lane;  // unit 0..63
    const int bg   = warp >> 1;               // batch group 0..3
    const int bb   = bg * 8;                  // first of 8 batches
    const int hoff = bb * 2;                  // col offset in dup rows

    // per-thread register copies of Wih0 gates and summed biases (as f32x2 pairs)
    u64 wxif[6], wxgo[6];
#pragma unroll
    for (int j = 0; j < 6; j++) {
        wxif[j] = pack2(Wih0[u * 6 + j],         Wih0[(64 + u) * 6 + j]);
        wxgo[j] = pack2(Wih0[(128 + u) * 6 + j], Wih0[(192 + u) * 6 + j]);
    }
    const u64 b0if = pack2(bih0[u] + bhh0[u],             bih0[64 + u] + bhh0[64 + u]);
    const u64 b0go = pack2(bih0[128 + u] + bhh0[128 + u], bih0[192 + u] + bhh0[192 + u]);
    const u64 b1if = pack2(bih1[u] + bhh1[u],             bih1[64 + u] + bhh1[64 + u]);
    const u64 b1go = pack2(bih1[128 + u] + bhh1[128 + u], bih1[192 + u] + bhh1[192 + u]);

    // x staging: 192 threads cover 32 batches x 6 features
    const bool doX = (tid < BC * 6);
    const int  xb  = tid / 6, xj = tid - xb * 6;
    const float* xbase = x + (size_t)(batch0 + xb) * (TT * 6) + xj;
    if (doX) s->xs[xj * 32 + xb] = xbase[0];
    __syncthreads();

    float* const myh0 = &s->h0[u * HS2 + hoff];
    float* const myh1 = &s->h1[u * HS2 + hoff];

    float c0[8], c1[8];
#pragma unroll
    for (int i = 0; i < 8; i++) { c0[i] = 0.f; c1[i] = 0.f; }

    for (int t = 0; t < TT; t++) {
        // prefetch x(t+1) into a register (hidden behind layer-0 GEMM)
        float xv = 0.f;
        if (doX && t + 1 < TT) xv = xbase[(size_t)(t + 1) * 6];

        // ================= layer 0: gates = b0 + Wih0 x_t + Whh0 h0 =================
        u64 aif[8], ago[8];
#pragma unroll
        for (int b = 0; b < 8; b++) { aif[b] = b0if; ago[b] = b0go; }

#pragma unroll
        for (int j = 0; j < 6; j++) {
            float4 xa = *(const float4*)&s->xs[j * 32 + bb];
            float4 xc = *(const float4*)&s->xs[j * 32 + bb + 4];
            u64 p;
            p = pack2(xa.x, xa.x); fma2(aif[0], p, wxif[j]); fma2(ago[0], p, wxgo[j]);
            p = pack2(xa.y, xa.y); fma2(aif[1], p, wxif[j]); fma2(ago[1], p, wxgo[j]);
            p = pack2(xa.z, xa.z); fma2(aif[2], p, wxif[j]); fma2(ago[2], p, wxgo[j]);
            p = pack2(xa.w, xa.w); fma2(aif[3], p, wxif[j]); fma2(ago[3], p, wxgo[j]);
            p = pack2(xc.x, xc.x); fma2(aif[4], p, wxif[j]); fma2(ago[4], p, wxgo[j]);
            p = pack2(xc.y, xc.y); fma2(aif[5], p, wxif[j]); fma2(ago[5], p, wxgo[j]);
            p = pack2(xc.z, xc.z); fma2(aif[6], p, wxif[j]); fma2(ago[6], p, wxgo[j]);
            p = pack2(xc.w, xc.w); fma2(aif[7], p, wxif[j]); fma2(ago[7], p, wxgo[j]);
        }
#pragma unroll 2
        for (int k = 0; k < 64; k++)
            macK(aif, ago, &s->h0[k * HS2 + hoff], &s->whh0[k * 64 + u]);
        __syncthreads();   // everyone done reading old h0 / xs

        epilogue(aif, ago, c0, myh0);          // publish new h0 (duplicated)
        if (doX && t + 1 < TT) s->xs[xj * 32 + xb] = xv;
        __syncthreads();   // new h0 (and next x) visible

        // ================= layer 1: gates = b1 + Wih1 h0_new + Whh1 h1 =================
#pragma unroll
        for (int b = 0; b < 8; b++) { aif[b] = b1if; ago[b] = b1go; }
#pragma unroll 2
        for (int k = 0; k < 64; k++) {
            macK(aif, ago, &s->h0[k * HS2 + hoff], &s->wih1[k * 64 + u]);
            macK(aif, ago, &s->h1[k * HS2 + hoff], &s->whh1[k * 64 + u]);
        }
        __syncthreads();   // everyone done reading old h1 (and h0)

        epilogue(aif, ago, c1, myh1);          // publish new h1
        // no trailing sync: next iteration's barriers order remaining hazards
    }
    __syncthreads();

    // ---- final FC: out[b] = h1_T @ Wfc^T + bfc ----
    if (tid < BC * 3) {
        int b = tid / 3, oc = tid - b * 3;
        float sum = bfc[oc];
#pragma unroll
        for (int k = 0; k < 64; k++)
            sum = fmaf(s->h1[k * HS2 + 2 * b], Wfc[oc * 64 + k], sum);
        out[(size_t)(batch0 + b) * 3 + oc] = sum;
    }
}

extern "C" void kernel_launch(void* const* d_in, const int* in_sizes, int n_in,
                              void* d_out, int out_size)
{
    (void)in_sizes; (void)n_in; (void)out_size;
    cudaFuncSetAttribute(lstm2_kernel, cudaFuncAttributeMaxDynamicSharedMemorySize,
                         (int)sizeof(SmemT));
    lstm2_kernel<<<NB / BC, NTH, sizeof(SmemT)>>>(
        (const float*)d_in[0],
        (const float*)d_in[1], (const float*)d_in[2],
        (const float*)d_in[3], (const float*)d_in[4],
        (const float*)d_in[5], (const float*)d_in[6],
        (const float*)d_in[7], (const float*)d_in[8],
        (const float*)d_in[9], (const float*)d_in[10],
        (float*)d_out);
}

// round 10
// speedup vs baseline: 3.6412x; 3.6412x over previous
#include <cuda_runtime.h>
#include <cuda_fp16.h>
#include <cstdint>
#include <cstddef>

#define TT   512
#define MB   32
#define NTH  256
#define GRID 128

// ---- shared memory byte offsets (h tiles: 32 rows x 64 units fp16, 128B rows, XOR-swizzled) ----
#define H0HI(b) ((b) ? 8192 : 0)
#define H0LO(b) ((b) ? 12288 : 4096)
#define H1HI(b) (16384 + ((b) ? 8192 : 0))
#define H1LO(b) (20480 + ((b) ? 8192 : 0))
#define XOFF(b) (32768 + (b) * 4096)
#define SMEMB   40960

__device__ __forceinline__ uint32_t smem_u32(const void* p) {
    uint32_t a;
    asm("{ .reg .u64 t; cvta.to.shared.u64 t, %1; cvt.u32.u64 %0, t; }" : "=r"(a) : "l"(p));
    return a;
}
__device__ __forceinline__ void ldmA(uint32_t* a, uint32_t saddr) {
    asm volatile("ldmatrix.sync.aligned.m8n8.x4.shared.b16 {%0,%1,%2,%3}, [%4];"
                 : "=r"(a[0]), "=r"(a[1]), "=r"(a[2]), "=r"(a[3]) : "r"(saddr));
}
__device__ __forceinline__ void mma16816(float* d, const uint32_t* a, const uint32_t* b) {
    asm volatile("mma.sync.aligned.m16n8k16.row.col.f32.f16.f16.f32 "
                 "{%0,%1,%2,%3}, {%4,%5,%6,%7}, {%8,%9}, {%0,%1,%2,%3};"
                 : "+f"(d[0]), "+f"(d[1]), "+f"(d[2]), "+f"(d[3])
                 : "r"(a[0]), "r"(a[1]), "r"(a[2]), "r"(a[3]), "r"(b[0]), "r"(b[1]));
}
__device__ __forceinline__ uint32_t f2h2(float a, float b) {
    __half2 h = __floats2half2_rn(a, b);
    return *reinterpret_cast<uint32_t*>(&h);
}
__device__ __forceinline__ float sigm(float x) {
    float e = __expf(-x);
    return __fdividef(1.0f, 1.0f + e);
}
__device__ __forceinline__ float tanh_f(float x) { return fmaf(2.0f, sigm(2.0f * x), -1.0f); }

// full K=64 pass: gates(32x32 warp tile) += h(32x64) @ W(64x32)
__device__ __forceinline__ void mma_pass(float acc[2][4][4], uint32_t abase,
                                         const uint32_t B[4][4][2]) {
#pragma unroll
    for (int kt = 0; kt < 4; kt++) {
        uint32_t a0[4], a1[4];
        // abase already includes lane row*128 and swizzle-ready col term
        ldmA(a0, abase + ((uint32_t)(kt * 32)) );  // placeholder; real addr below
        (void)a1;
    }
}

__global__ void __launch_bounds__(NTH, 1) lstm2_hmma(
    const float* __restrict__ x,
    const float* __restrict__ Wih0, const float* __restrict__ Whh0,
    const float* __restrict__ bih0, const float* __restrict__ bhh0,
    const float* __restrict__ Wih1, const float* __restrict__ Whh1,
    const float* __restrict__ bih1, const float* __restrict__ bhh1,
    const float* __restrict__ Wfc,  const float* __restrict__ bfc,
    float* __restrict__ out)
{
    __shared__ __align__(16) char sm[SMEMB];
    const uint32_t smb = smem_u32(sm);
    const int tid  = threadIdx.x;
    const int wid  = tid >> 5;
    const int lane = tid & 31;
    const int tg   = lane & 3;          // thread-in-group (col pair selector)
    const int q    = lane >> 2;         // row within 8
    const int odd  = tg & 1;
    const int batch0 = blockIdx.x * MB;

    // ---- zero h + x regions ----
    for (int i = tid; i < SMEMB / 16; i += NTH) ((uint4*)sm)[i] = make_uint4(0, 0, 0, 0);

    // ---- weight B-fragments into registers (one-time, fp16) ----
    // B frag (k16 x n8): b0 = W^T[k0..k0+1][n], b1 = W^T[k0+8..k0+9][n]; k0=tg*2, n=lane>>2
    const int n_l = lane >> 2;
    uint32_t Bhh0[4][4][2], Bih1[4][4][2], Bhh1[4][4][2], Bx[4][2];
#pragma unroll
    for (int nt = 0; nt < 4; nt++) {
        const int cg = wid * 32 + nt * 8 + n_l;      // global gate column
        const int u = cg >> 2, g = cg & 3;
        const float* r0 = Whh0 + (g * 64 + u) * 64;
        const float* r1 = Wih1 + (g * 64 + u) * 64;
        const float* r2 = Whh1 + (g * 64 + u) * 64;
#pragma unroll
        for (int kt = 0; kt < 4; kt++) {
            const int k0 = kt * 16 + tg * 2;
            Bhh0[kt][nt][0] = f2h2(r0[k0],     r0[k0 + 1]);
            Bhh0[kt][nt][1] = f2h2(r0[k0 + 8], r0[k0 + 9]);
            Bih1[kt][nt][0] = f2h2(r1[k0],     r1[k0 + 1]);
            Bih1[kt][nt][1] = f2h2(r1[k0 + 8], r1[k0 + 9]);
            Bhh1[kt][nt][0] = f2h2(r2[k0],     r2[k0 + 1]);
            Bhh1[kt][nt][1] = f2h2(r2[k0 + 8], r2[k0 + 9]);
        }
        // x weights: Kdim=6, k-tile 0 only; pad k>=6 with zero
        const float* rx = Wih0 + (g * 64 + u) * 6;
        const int k0 = tg * 2;
        float w0 = (k0     < 6) ? rx[k0]     : 0.0f;
        float w1 = (k0 + 1 < 6) ? rx[k0 + 1] : 0.0f;
        Bx[nt][0] = f2h2(w0, w1);
        Bx[nt][1] = 0u;                                   // k 8..15 zero
    }
    // summed biases for my two columns (tg*2, tg*2+1) per n-tile
    float b0r[8], b1r[8];
#pragma unroll
    for (int nt = 0; nt < 4; nt++) {
#pragma unroll
        for (int j = 0; j < 2; j++) {
            const int cg = wid * 32 + nt * 8 + tg * 2 + j;
            const int u = cg >> 2, g = cg & 3, idx = g * 64 + u;
            b0r[nt * 2 + j] = bih0[idx] + bhh0[idx];
            b1r[nt * 2 + j] = bih1[idx] + bhh1[idx];
        }
    }

    // ---- stage x(0) ----
    if (tid < MB) {
        const float2* xp = (const float2*)(x + (size_t)(batch0 + tid) * TT * 6);
        float2 a = xp[0], b = xp[1], c = xp[2];
        char* p = sm + XOFF(0) + tid * 128 + ((tid & 7) << 4);
        ((uint32_t*)p)[0] = f2h2(a.x, a.y);
        ((uint32_t*)p)[1] = f2h2(b.x, b.y);
        ((uint32_t*)p)[2] = f2h2(c.x, c.y);
    }
    __syncthreads();

    // ldmatrix lane addressing (A 16x16 tiles from 32x64 fp16, 128B rows, XOR swizzle)
    const uint32_t laneRow = (uint32_t)(lane & 15);
    const uint32_t sw      = (uint32_t)((lane & 7) << 4);
    const uint32_t col16   = (uint32_t)(lane & 16);
    const uint32_t laneTerm = laneRow * 128;   // + ((kt*32 + col16) ^ sw) per tile

    float cst0[8], cst1[8];
#pragma unroll
    for (int i = 0; i < 8; i++) { cst0[i] = 0.0f; cst1[i] = 0.0f; }

    float acc[2][4][4];

    for (int t = 0; t < TT; t++) {
        const int cur = t & 1, prv = cur ^ 1;

        // prefetch x(t+1)
        float2 xa, xb, xc;
        if (tid < MB && t + 1 < TT) {
            const float2* xp = (const float2*)(x + ((size_t)(batch0 + tid) * TT + (t + 1)) * 6);
            xa = xp[0]; xb = xp[1]; xc = xp[2];
        }

        // ================= layer 0 =================
#pragma unroll
        for (int mt = 0; mt < 2; mt++)
#pragma unroll
            for (int nt = 0; nt < 4; nt++) {
                acc[mt][nt][0] = b0r[nt * 2];     acc[mt][nt][1] = b0r[nt * 2 + 1];
                acc[mt][nt][2] = b0r[nt * 2];     acc[mt][nt][3] = b0r[nt * 2 + 1];
            }
#pragma unroll
        for (int pass = 0; pass < 2; pass++) {
            const uint32_t hb = smb + (pass == 0 ? (uint32_t)H0HI(prv) : (uint32_t)H0LO(prv)) + laneTerm;
#pragma unroll
            for (int kt = 0; kt < 4; kt++) {
                uint32_t a0[4], a1[4];
                const uint32_t coff = (uint32_t)((kt * 32 + col16)) ^ sw;
                ldmA(a0, hb + coff);
                ldmA(a1, hb + 2048 + coff);
#pragma unroll
                for (int nt = 0; nt < 4; nt++) {
                    mma16816(acc[0][nt], a0, Bhh0[kt][nt]);
                    mma16816(acc[1][nt], a1, Bhh0[kt][nt]);
                }
            }
        }
        {   // x contribution (k-tile 0 only)
            const uint32_t xb_ = smb + (uint32_t)XOFF(cur) + laneTerm;
            uint32_t a0[4], a1[4];
            const uint32_t coff = col16 ^ sw;
            ldmA(a0, xb_ + coff);
            ldmA(a1, xb_ + 2048 + coff);
#pragma unroll
            for (int nt = 0; nt < 4; nt++) {
                mma16816(acc[0][nt], a0, Bx[nt]);
                mma16816(acc[1][nt], a1, Bx[nt]);
            }
        }
        // epilogue 0 -> h0[cur]
#pragma unroll
        for (int mt = 0; mt < 2; mt++)
#pragma unroll
            for (int nt = 0; nt < 4; nt++) {
                float* d = acc[mt][nt];
                float s0 = odd ? d[0] : d[2];
                float s1 = odd ? d[1] : d[3];
                float r0 = __shfl_xor_sync(0xffffffffu, s0, 1);
                float r1 = __shfl_xor_sync(0xffffffffu, s1, 1);
                float gi = odd ? r0 : d[0], gf = odd ? r1 : d[1];
                float gg = odd ? d[2] : r0, go = odd ? d[3] : r1;
                float i_ = sigm(gi), f_ = sigm(gf), g_ = tanh_f(gg), o_ = sigm(go);
                float c = fmaf(f_, cst0[mt * 4 + nt], i_ * g_);
                cst0[mt * 4 + nt] = c;
                float h = o_ * tanh_f(c);
                const int u   = wid * 8 + nt * 2 + (tg >> 1);
                const int row = mt * 16 + q + odd * 8;
                const int bo  = row * 128 + ((u * 2) ^ ((row & 7) << 4));
                __half hh = __float2half_rn(h);
                __half hl = __float2half_rn(h - __half2float(hh));
                *(__half*)(sm + H0HI(cur) + bo) = hh;
                *(__half*)(sm + H0LO(cur) + bo) = hl;
            }
        if (tid < MB && t + 1 < TT) {   // publish x(t+1)
            char* p = sm + XOFF(prv) + tid * 128 + ((tid & 7) << 4);
            ((uint32_t*)p)[0] = f2h2(xa.x, xa.y);
            ((uint32_t*)p)[1] = f2h2(xb.x, xb.y);
            ((uint32_t*)p)[2] = f2h2(xc.x, xc.y);
        }
        __syncthreads();

        // ================= layer 1 =================
#pragma unroll
        for (int mt = 0; mt < 2; mt++)
#pragma unroll
            for (int nt = 0; nt < 4; nt++) {
                acc[mt][nt][0] = b1r[nt * 2];     acc[mt][nt][1] = b1r[nt * 2 + 1];
                acc[mt][nt][2] = b1r[nt * 2];     acc[mt][nt][3] = b1r[nt * 2 + 1];
            }
#pragma unroll
        for (int pass = 0; pass < 4; pass++) {
            uint32_t hoff;
            if      (pass == 0) hoff = (uint32_t)H0HI(cur);
            else if (pass == 1) hoff = (uint32_t)H0LO(cur);
            else if (pass == 2) hoff = (uint32_t)H1HI(prv);
            else                hoff = (uint32_t)H1LO(prv);
            const uint32_t hb = smb + hoff + laneTerm;
#pragma unroll
            for (int kt = 0; kt < 4; kt++) {
                uint32_t a0[4], a1[4];
                const uint32_t coff = (uint32_t)((kt * 32 + col16)) ^ sw;
                ldmA(a0, hb + coff);
                ldmA(a1, hb + 2048 + coff);
#pragma unroll
                for (int nt = 0; nt < 4; nt++) {
                    const uint32_t* B = (pass < 2) ? Bih1[kt][nt] : Bhh1[kt][nt];
                    mma16816(acc[0][nt], a0, B);
                    mma16816(acc[1][nt], a1, B);
                }
            }
        }
        // epilogue 1 -> h1[cur]
#pragma unroll
        for (int mt = 0; mt < 2; mt++)
#pragma unroll
            for (int nt = 0; nt < 4; nt++) {
                float* d = acc[mt][nt];
                float s0 = odd ? d[0] : d[2];
                float s1 = odd ? d[1] : d[3];
                float r0 = __shfl_xor_sync(0xffffffffu, s0, 1);
                float r1 = __shfl_xor_sync(0xffffffffu, s1, 1);
                float gi = odd ? r0 : d[0], gf = odd ? r1 : d[1];
                float gg = odd ? d[2] : r0, go = odd ? d[3] : r1;
                float i_ = sigm(gi), f_ = sigm(gf), g_ = tanh_f(gg), o_ = sigm(go);
                float c = fmaf(f_, cst1[mt * 4 + nt], i_ * g_);
                cst1[mt * 4 + nt] = c;
                float h = o_ * tanh_f(c);
                const int u   = wid * 8 + nt * 2 + (tg >> 1);
                const int row = mt * 16 + q + odd * 8;
                const int bo  = row * 128 + ((u * 2) ^ ((row & 7) << 4));
                __half hh = __float2half_rn(h);
                __half hl = __float2half_rn(h - __half2float(hh));
                *(__half*)(sm + H1HI(cur) + bo) = hh;
                *(__half*)(sm + H1LO(cur) + bo) = hl;
            }
        __syncthreads();
    }

    // ---- final FC from h1[(TT-1)&1 = 1]: out = h1 @ Wfc^T + bfc ----
    if (tid < MB * 3) {
        const int b = tid / 3, oc = tid - b * 3;
        float s = bfc[oc];
#pragma unroll 8
        for (int u = 0; u < 64; u++) {
            const int bo = b * 128 + ((u * 2) ^ ((b & 7) << 4));
            float h = __half2float(*(const __half*)(sm + H1HI(1) + bo))
                    + __half2float(*(const __half*)(sm + H1LO(1) + bo));
            s = fmaf(h, Wfc[oc * 64 + u], s);
        }
        out[(size_t)(batch0 + b) * 3 + oc] = s;
    }
}

extern "C" void kernel_launch(void* const* d_in, const int* in_sizes, int n_in,
                              void* d_out, int out_size)
{
    (void)in_sizes; (void)n_in; (void)out_size;
    lstm2_hmma<<<GRID, NTH>>>(
        (const float*)d_in[0],
        (const float*)d_in[1], (const float*)d_in[2],
        (const float*)d_in[3], (const float*)d_in[4],
        (const float*)d_in[5], (const float*)d_in[6],
        (const float*)d_in[7], (const float*)d_in[8],
        (const float*)d_in[9], (const float*)d_in[10],
        (float*)d_out);
}